// round 8
// baseline (speedup 1.0000x reference)
#include <cuda_runtime.h>
#include <cuda_bf16.h>
#include <cstdint>

#define BATCH 16
#define SEQ   2048
#define DIM   128
#define BM    128
#define BN    64
#define KTILES (SEQ / BN)
#define NTHREADS 256

// Pre-converted K/V tiles in gmem: per (b,kt) 64 KB: [K_HI 16K][K_LO 16K][V_HI 16K][V_LO 16K]
// each sub-tile 64 rows x 256 B with the XOR-16B-chunk swizzle baked in.
#define KV_TILE_BYTES 65536
__device__ unsigned char g_kv[(size_t)BATCH * KTILES * KV_TILE_BYTES];  // 32 MB

// SMEM rings: K double-buffer, V double-buffer, Q hi/lo
#define SM_K0   0
#define SM_K1   32768
#define SM_V0   65536
#define SM_V1   98304
#define SM_QHI  131072
#define SM_QLO  163840
#define SM_TOTAL 196608

__device__ __forceinline__ uint32_t smem_u32(const void* p) {
    uint32_t a;
    asm("{ .reg .u64 t; cvta.to.shared.u64 t, %1; cvt.u32.u64 %0, t; }" : "=r"(a) : "l"(p));
    return a;
}
__device__ __forceinline__ uint32_t swz(int r, int c4) {
    return (uint32_t)(r * 256 + ((((c4 >> 1) ^ (r & 7)) << 4) | ((c4 & 1) << 3)));
}
__device__ __forceinline__ void ldsm_x4(uint32_t* r, uint32_t a) {
    asm volatile("ldmatrix.sync.aligned.m8n8.x4.shared.b16 {%0,%1,%2,%3}, [%4];"
        : "=r"(r[0]), "=r"(r[1]), "=r"(r[2]), "=r"(r[3]) : "r"(a));
}
__device__ __forceinline__ void ldsm_x4_t(uint32_t* r, uint32_t a) {
    asm volatile("ldmatrix.sync.aligned.m8n8.x4.trans.shared.b16 {%0,%1,%2,%3}, [%4];"
        : "=r"(r[0]), "=r"(r[1]), "=r"(r[2]), "=r"(r[3]) : "r"(a));
}
__device__ __forceinline__ void mma_bf16(float* c, const uint32_t* a, uint32_t b0, uint32_t b1) {
    asm volatile("mma.sync.aligned.m16n8k16.row.col.f32.bf16.bf16.f32 "
        "{%0,%1,%2,%3}, {%4,%5,%6,%7}, {%8,%9}, {%0,%1,%2,%3};"
        : "+f"(c[0]), "+f"(c[1]), "+f"(c[2]), "+f"(c[3])
        : "r"(a[0]), "r"(a[1]), "r"(a[2]), "r"(a[3]), "r"(b0), "r"(b1));
}
__device__ __forceinline__ uint32_t pack_bf16(float lo, float hi) {
    __nv_bfloat162 t = __floats2bfloat162_rn(lo, hi);
    return *reinterpret_cast<uint32_t*>(&t);
}
__device__ __forceinline__ void cvt_split(float4 v, uint2& hi, uint2& lo) {
    __nv_bfloat162 h01 = __floats2bfloat162_rn(v.x, v.y);
    __nv_bfloat162 h23 = __floats2bfloat162_rn(v.z, v.w);
    float rx = v.x - __bfloat162float(h01.x);
    float ry = v.y - __bfloat162float(h01.y);
    float rz = v.z - __bfloat162float(h23.x);
    float rw = v.w - __bfloat162float(h23.y);
    __nv_bfloat162 l01 = __floats2bfloat162_rn(rx, ry);
    __nv_bfloat162 l23 = __floats2bfloat162_rn(rz, rw);
    hi = make_uint2(*reinterpret_cast<uint32_t*>(&h01), *reinterpret_cast<uint32_t*>(&h23));
    lo = make_uint2(*reinterpret_cast<uint32_t*>(&l01), *reinterpret_cast<uint32_t*>(&l23));
}
__device__ __forceinline__ float ex2f(float x) {
    float y;
    asm("ex2.approx.ftz.f32 %0, %1;" : "=f"(y) : "f"(x));
    return y;
}
__device__ __forceinline__ void cp_async16(uint32_t dst, const void* src) {
    asm volatile("cp.async.ca.shared.global [%0], [%1], 16;" :: "r"(dst), "l"(src));
}

// ---------------- pre-pass: K,V f32 -> swizzled bf16 hi/lo tiles ----------------
__global__ __launch_bounds__(256)
void kv_prepass(const float* __restrict__ K, const float* __restrict__ V)
{
    int i = blockIdx.x * 256 + threadIdx.x;
    int b   = i >> 16;
    int rem = i & 65535;
    int rg  = rem >> 5;
    int c4  = rem & 31;
    int kt  = rg >> 6;
    int r   = rg & 63;

    size_t src = ((size_t)b * SEQ + rg) * DIM + c4 * 4;
    float4 kv = *(const float4*)(K + src);
    float4 vv = *(const float4*)(V + src);

    unsigned char* dst = g_kv + (size_t)(b * KTILES + kt) * KV_TILE_BYTES;
    uint32_t so = swz(r, c4);
    uint2 hi, lo;
    cvt_split(kv, hi, lo);
    *(uint2*)(dst + 0     + so) = hi;
    *(uint2*)(dst + 16384 + so) = lo;
    cvt_split(vv, hi, lo);
    *(uint2*)(dst + 32768 + so) = hi;
    *(uint2*)(dst + 49152 + so) = lo;
}

// ---------------- main kernel ----------------
__global__ __launch_bounds__(NTHREADS, 1)
void attn_mma_kernel(const float* __restrict__ Q, const float* __restrict__ scale,
                     float* __restrict__ Out)
{
    extern __shared__ char smem[];
    const uint32_t sb = smem_u32(smem);

    const int tid  = threadIdx.x;
    const int wid  = tid >> 5;
    const int lane = tid & 31;
    const int g    = lane >> 2;
    const int t4   = lane & 3;
    const int wr   = wid * 16;
    const int q0   = blockIdx.x * BM;
    const int b    = blockIdx.y;
    const int m7   = lane & 7;
    const float L2E = 1.4426950408889634f;

    const float* Qb = Q + (size_t)b * SEQ * DIM;
    const unsigned char* gkv = g_kv + (size_t)b * KTILES * KV_TILE_BYTES;

    const uint32_t hcA = (lane >> 4) & 1;
    const uint32_t hcB = (lane >> 3) & 1;
    const uint32_t hcV = (lane >> 4) & 1;
    const uint32_t qrow  = (uint32_t)(wr + m7 + ((lane >> 3) & 1) * 8);
    const uint32_t krowl = (uint32_t)(m7 + ((lane >> 4) & 1) * 8);
    const uint32_t vrowl = (uint32_t)(lane & 15);
    const uint32_t qbase = sb + SM_QHI + qrow * 256;

    const float* sp0 = scale + (size_t)(q0 + wr + g) * SEQ + 2 * t4;
    const float* sp1 = sp0 + 8 * SEQ;

    // ---- prologue prefetch: K0, V0, K1 in one group ----
    {
        const unsigned char* s0 = gkv;                       // K0
        #pragma unroll
        for (int u = 0; u < 8; u++) {
            int idx = tid + u * NTHREADS;
            cp_async16(sb + SM_K0 + idx * 16, s0 + idx * 16);
        }
        const unsigned char* s1 = gkv + 32768;               // V0
        #pragma unroll
        for (int u = 0; u < 8; u++) {
            int idx = tid + u * NTHREADS;
            cp_async16(sb + SM_V0 + idx * 16, s1 + idx * 16);
        }
        const unsigned char* s2 = gkv + KV_TILE_BYTES;       // K1
        #pragma unroll
        for (int u = 0; u < 8; u++) {
            int idx = tid + u * NTHREADS;
            cp_async16(sb + SM_K1 + idx * 16, s2 + idx * 16);
        }
        asm volatile("cp.async.commit_group;" ::: "memory");
    }

    // ---- stage Q tile (hi/lo, swizzled) ----
    for (int i = tid; i < BM * 32; i += NTHREADS) {
        int r = i >> 5, c4 = i & 31;
        float4 v = *(const float4*)(Qb + (size_t)(q0 + r) * DIM + c4 * 4);
        uint2 hi, lo; cvt_split(v, hi, lo);
        uint32_t so = swz(r, c4);
        *(uint2*)(smem + SM_QHI + so) = hi;
        *(uint2*)(smem + SM_QLO + so) = lo;
    }

    float o[16][4];
    #pragma unroll
    for (int j = 0; j < 16; j++)
        { o[j][0] = 0.f; o[j][1] = 0.f; o[j][2] = 0.f; o[j][3] = 0.f; }
    float m0 = -1e30f, m1 = -1e30f, l0 = 0.f, l1 = 0.f;
    float sA[8][4], sB[8][4];

    // QK issue for tile ktN into accumulator sN (reads kbuf[ktN&1])
    auto qk_issue = [&](int ktN, float (&sN)[8][4]) {
        #pragma unroll
        for (int j = 0; j < 8; j++)
            { sN[j][0] = 0.f; sN[j][1] = 0.f; sN[j][2] = 0.f; sN[j][3] = 0.f; }
        const uint32_t kbase = sb + ((ktN & 1) ? SM_K1 : SM_K0) + krowl * 256;
        #pragma unroll
        for (int kc = 0; kc < 8; kc++) {
            uint32_t aoff = ((2u * kc + hcA) ^ m7) << 4;
            uint32_t boff = ((2u * kc + hcB) ^ m7) << 4;
            uint32_t ah[4], al[4], bh[4][4], bl[4][4];
            ldsm_x4(ah, qbase + aoff);
            ldsm_x4(al, qbase + 32768 + aoff);
            #pragma unroll
            for (int jp = 0; jp < 4; jp++) {
                uint32_t ka = kbase + jp * 4096u + boff;
                ldsm_x4(bh[jp], ka);
                ldsm_x4(bl[jp], ka + 16384);
            }
            #pragma unroll
            for (int jp = 0; jp < 4; jp++) {
                mma_bf16(sN[2*jp],   ah, bh[jp][0], bh[jp][1]);
                mma_bf16(sN[2*jp+1], ah, bh[jp][2], bh[jp][3]);
                mma_bf16(sN[2*jp],   ah, bl[jp][0], bl[jp][1]);
                mma_bf16(sN[2*jp+1], ah, bl[jp][2], bl[jp][3]);
                mma_bf16(sN[2*jp],   al, bh[jp][0], bh[jp][1]);
                mma_bf16(sN[2*jp+1], al, bh[jp][2], bh[jp][3]);
            }
        }
    };

    // one pipelined iteration: consume sC (tile kt), issue QK(kt+1) into sN first
    auto body = [&](int kt, float (&sC)[8][4], float (&sN)[8][4]) {
        // drain group committed last iteration, make copies visible, then prefetch
        asm volatile("cp.async.wait_group 0;" ::: "memory");
        __syncthreads();
        if (kt + 2 < KTILES) {
            const unsigned char* src = gkv + (size_t)(kt + 2) * KV_TILE_BYTES;  // K part
            uint32_t dst = sb + ((kt & 1) ? SM_K1 : SM_K0);
            #pragma unroll
            for (int u = 0; u < 8; u++) {
                int idx = tid + u * NTHREADS;
                cp_async16(dst + idx * 16, src + idx * 16);
            }
        }
        if (kt + 1 < KTILES) {
            const unsigned char* src = gkv + (size_t)(kt + 1) * KV_TILE_BYTES + 32768; // V part
            uint32_t dst = sb + (((kt + 1) & 1) ? SM_V1 : SM_V0);
            #pragma unroll
            for (int u = 0; u < 8; u++) {
                int idx = tid + u * NTHREADS;
                cp_async16(dst + idx * 16, src + idx * 16);
            }
        }
        asm volatile("cp.async.commit_group;" ::: "memory");

        // ---- issue next tile's QK: tensor pipe stays busy under softmax ----
        if (kt + 1 < KTILES) qk_issue(kt + 1, sN);

        // ---- softmax(kt): scale (log2e folded) + online max/exp ----
        float2 scA[8], scB[8];
        #pragma unroll
        for (int j = 0; j < 8; j++) {
            float2 a = __ldg((const float2*)(sp0 + (size_t)kt * BN + 8 * j));
            float2 c = __ldg((const float2*)(sp1 + (size_t)kt * BN + 8 * j));
            scA[j] = make_float2(a.x * L2E, a.y * L2E);
            scB[j] = make_float2(c.x * L2E, c.y * L2E);
        }
        float mx0 = -1e30f, mx1 = -1e30f;
        #pragma unroll
        for (int j = 0; j < 8; j++) {
            sC[j][0] *= scA[j].x; sC[j][1] *= scA[j].y;
            sC[j][2] *= scB[j].x; sC[j][3] *= scB[j].y;
            mx0 = fmaxf(mx0, fmaxf(sC[j][0], sC[j][1]));
            mx1 = fmaxf(mx1, fmaxf(sC[j][2], sC[j][3]));
        }
        mx0 = fmaxf(mx0, __shfl_xor_sync(0xffffffffu, mx0, 1));
        mx0 = fmaxf(mx0, __shfl_xor_sync(0xffffffffu, mx0, 2));
        mx1 = fmaxf(mx1, __shfl_xor_sync(0xffffffffu, mx1, 1));
        mx1 = fmaxf(mx1, __shfl_xor_sync(0xffffffffu, mx1, 2));

        float mn0 = fmaxf(m0, mx0), mn1 = fmaxf(m1, mx1);
        float a0 = ex2f(m0 - mn0),  a1 = ex2f(m1 - mn1);
        float sum0 = 0.f, sum1 = 0.f;
        #pragma unroll
        for (int j = 0; j < 8; j++) {
            sC[j][0] = ex2f(sC[j][0] - mn0); sum0 += sC[j][0];
            sC[j][1] = ex2f(sC[j][1] - mn0); sum0 += sC[j][1];
            sC[j][2] = ex2f(sC[j][2] - mn1); sum1 += sC[j][2];
            sC[j][3] = ex2f(sC[j][3] - mn1); sum1 += sC[j][3];
        }
        l0 = l0 * a0 + sum0; m0 = mn0;
        l1 = l1 * a1 + sum1; m1 = mn1;
        if (a0 != 1.0f || a1 != 1.0f) {
            #pragma unroll
            for (int j = 0; j < 16; j++) {
                o[j][0] *= a0; o[j][1] *= a0;
                o[j][2] *= a1; o[j][3] *= a1;
            }
        }

        // ---- PV(kt): O += P V ----
        const uint32_t vbase = sb + ((kt & 1) ? SM_V1 : SM_V0) + vrowl * 256;
        #pragma unroll
        for (int c = 0; c < 4; c++) {
            uint32_t ph[4], pl[4];
            {
                __nv_bfloat162 h; float r0, r1;
                h = __floats2bfloat162_rn(sC[2*c][0], sC[2*c][1]); ph[0] = *(uint32_t*)&h;
                r0 = sC[2*c][0] - __bfloat162float(h.x); r1 = sC[2*c][1] - __bfloat162float(h.y);
                pl[0] = pack_bf16(r0, r1);
                h = __floats2bfloat162_rn(sC[2*c][2], sC[2*c][3]); ph[1] = *(uint32_t*)&h;
                r0 = sC[2*c][2] - __bfloat162float(h.x); r1 = sC[2*c][3] - __bfloat162float(h.y);
                pl[1] = pack_bf16(r0, r1);
                h = __floats2bfloat162_rn(sC[2*c+1][0], sC[2*c+1][1]); ph[2] = *(uint32_t*)&h;
                r0 = sC[2*c+1][0] - __bfloat162float(h.x); r1 = sC[2*c+1][1] - __bfloat162float(h.y);
                pl[2] = pack_bf16(r0, r1);
                h = __floats2bfloat162_rn(sC[2*c+1][2], sC[2*c+1][3]); ph[3] = *(uint32_t*)&h;
                r0 = sC[2*c+1][2] - __bfloat162float(h.x); r1 = sC[2*c+1][3] - __bfloat162float(h.y);
                pl[3] = pack_bf16(r0, r1);
            }
            #pragma unroll
            for (int half = 0; half < 2; half++) {
                uint32_t vh[4][4], vl[4][4];
                #pragma unroll
                for (int q = 0; q < 4; q++) {
                    int jp = 4 * half + q;
                    uint32_t va = vbase + c * 4096u + (((2u * jp + hcV) ^ m7) << 4);
                    ldsm_x4_t(vh[q], va);
                    ldsm_x4_t(vl[q], va + 16384);
                }
                #pragma unroll
                for (int q = 0; q < 4; q++) {
                    int jp = 4 * half + q;
                    mma_bf16(o[2*jp],   ph, vh[q][0], vh[q][1]);
                    mma_bf16(o[2*jp+1], ph, vh[q][2], vh[q][3]);
                    mma_bf16(o[2*jp],   ph, vl[q][0], vl[q][1]);
                    mma_bf16(o[2*jp+1], ph, vl[q][2], vl[q][3]);
                    mma_bf16(o[2*jp],   pl, vh[q][0], vh[q][1]);
                    mma_bf16(o[2*jp+1], pl, vh[q][2], vh[q][3]);
                }
            }
        }
    };

    // ---- prologue compute: wait K0/V0/K1, QK(0) ----
    asm volatile("cp.async.wait_group 0;" ::: "memory");
    __syncthreads();
    qk_issue(0, sA);

    #pragma unroll 1
    for (int kt2 = 0; kt2 < KTILES; kt2 += 2) {
        body(kt2,     sA, sB);
        body(kt2 + 1, sB, sA);
    }

    // ---- epilogue: reduce per-lane denominators across the t4 quad ----
    l0 += __shfl_xor_sync(0xffffffffu, l0, 1);
    l0 += __shfl_xor_sync(0xffffffffu, l0, 2);
    l1 += __shfl_xor_sync(0xffffffffu, l1, 1);
    l1 += __shfl_xor_sync(0xffffffffu, l1, 2);
    float inv0 = 1.f / l0, inv1 = 1.f / l1;
    float* out0 = Out + (size_t)((size_t)b * SEQ + q0 + wr + g) * DIM;
    float* out1 = out0 + 8 * DIM;
    #pragma unroll
    for (int j = 0; j < 16; j++) {
        int col = 8 * j + 2 * t4;
        *(float2*)(out0 + col) = make_float2(o[j][0] * inv0, o[j][1] * inv0);
        *(float2*)(out1 + col) = make_float2(o[j][2] * inv1, o[j][3] * inv1);
    }
}

extern "C" void kernel_launch(void* const* d_in, const int* in_sizes, int n_in,
                              void* d_out, int out_size)
{
    const float* Q     = (const float*)d_in[0];
    const float* K     = (const float*)d_in[1];
    const float* V     = (const float*)d_in[2];
    const float* scale = (const float*)d_in[3];
    float* O = (float*)d_out;

    kv_prepass<<<(BATCH * SEQ * 32) / 256, 256>>>(K, V);

    cudaFuncSetAttribute(attn_mma_kernel,
                         cudaFuncAttributeMaxDynamicSharedMemorySize, SM_TOTAL);
    dim3 grid(SEQ / BM, BATCH);
    attn_mma_kernel<<<grid, NTHREADS, SM_TOTAL>>>(Q, scale, O);
}

// round 9
// speedup vs baseline: 1.3325x; 1.3325x over previous
#include <cuda_runtime.h>
#include <cuda_bf16.h>
#include <cuda_fp16.h>
#include <cstdint>

#define BATCH 16
#define SEQ   2048
#define DIM   128
#define BM    128
#define BN    64
#define KTILES (SEQ / BN)
#define NTHREADS 256

// Pre-converted K/V tiles: per (b,kt) 48 KB: [K_HI 16K][K_LO 16K][V_F16 16K]
// each sub-tile 64 rows x 256 B, XOR-16B-chunk swizzle baked in.
#define KV_TILE_BYTES 49152
__device__ unsigned char g_kv[(size_t)BATCH * KTILES * KV_TILE_BYTES];  // 24 MB

#define OFF_KHI 0
#define OFF_KLO 16384
#define OFF_V   32768

#define SM_STAGE0 0
#define SM_STAGE1 49152
#define SM_QHI    98304
#define SM_QLO    131072
#define SM_TOTAL  163840

__device__ __forceinline__ uint32_t smem_u32(const void* p) {
    uint32_t a;
    asm("{ .reg .u64 t; cvta.to.shared.u64 t, %1; cvt.u32.u64 %0, t; }" : "=r"(a) : "l"(p));
    return a;
}
__device__ __forceinline__ uint32_t swz(int r, int c4) {
    return (uint32_t)(r * 256 + ((((c4 >> 1) ^ (r & 7)) << 4) | ((c4 & 1) << 3)));
}
__device__ __forceinline__ void ldsm_x4(uint32_t* r, uint32_t a) {
    asm volatile("ldmatrix.sync.aligned.m8n8.x4.shared.b16 {%0,%1,%2,%3}, [%4];"
        : "=r"(r[0]), "=r"(r[1]), "=r"(r[2]), "=r"(r[3]) : "r"(a));
}
__device__ __forceinline__ void ldsm_x4_t(uint32_t* r, uint32_t a) {
    asm volatile("ldmatrix.sync.aligned.m8n8.x4.trans.shared.b16 {%0,%1,%2,%3}, [%4];"
        : "=r"(r[0]), "=r"(r[1]), "=r"(r[2]), "=r"(r[3]) : "r"(a));
}
__device__ __forceinline__ void mma_bf16(float* c, const uint32_t* a, uint32_t b0, uint32_t b1) {
    asm volatile("mma.sync.aligned.m16n8k16.row.col.f32.bf16.bf16.f32 "
        "{%0,%1,%2,%3}, {%4,%5,%6,%7}, {%8,%9}, {%0,%1,%2,%3};"
        : "+f"(c[0]), "+f"(c[1]), "+f"(c[2]), "+f"(c[3])
        : "r"(a[0]), "r"(a[1]), "r"(a[2]), "r"(a[3]), "r"(b0), "r"(b1));
}
__device__ __forceinline__ void mma_f16(float* c, const uint32_t* a, uint32_t b0, uint32_t b1) {
    asm volatile("mma.sync.aligned.m16n8k16.row.col.f32.f16.f16.f32 "
        "{%0,%1,%2,%3}, {%4,%5,%6,%7}, {%8,%9}, {%0,%1,%2,%3};"
        : "+f"(c[0]), "+f"(c[1]), "+f"(c[2]), "+f"(c[3])
        : "r"(a[0]), "r"(a[1]), "r"(a[2]), "r"(a[3]), "r"(b0), "r"(b1));
}
__device__ __forceinline__ void cvt_split(float4 v, uint2& hi, uint2& lo) {
    __nv_bfloat162 h01 = __floats2bfloat162_rn(v.x, v.y);
    __nv_bfloat162 h23 = __floats2bfloat162_rn(v.z, v.w);
    float rx = v.x - __bfloat162float(h01.x);
    float ry = v.y - __bfloat162float(h01.y);
    float rz = v.z - __bfloat162float(h23.x);
    float rw = v.w - __bfloat162float(h23.y);
    __nv_bfloat162 l01 = __floats2bfloat162_rn(rx, ry);
    __nv_bfloat162 l23 = __floats2bfloat162_rn(rz, rw);
    hi = make_uint2(*reinterpret_cast<uint32_t*>(&h01), *reinterpret_cast<uint32_t*>(&h23));
    lo = make_uint2(*reinterpret_cast<uint32_t*>(&l01), *reinterpret_cast<uint32_t*>(&l23));
}
__device__ __forceinline__ float ex2f(float x) {
    float y;
    asm("ex2.approx.ftz.f32 %0, %1;" : "=f"(y) : "f"(x));
    return y;
}
__device__ __forceinline__ uint32_t pack_f16(float a, float b) {
    __half2 h = __floats2half2_rn(a, b);
    return *reinterpret_cast<uint32_t*>(&h);
}
__device__ __forceinline__ void cp_async16(uint32_t dst, const void* src) {
    asm volatile("cp.async.ca.shared.global [%0], [%1], 16;" :: "r"(dst), "l"(src));
}

// ---------------- pre-pass: K -> bf16 hi/lo, V -> f16, swizzled tiles ----------------
__global__ __launch_bounds__(256)
void kv_prepass(const float* __restrict__ K, const float* __restrict__ V)
{
    int i = blockIdx.x * 256 + threadIdx.x;
    int b   = i >> 16;
    int rem = i & 65535;
    int rg  = rem >> 5;
    int c4  = rem & 31;
    int kt  = rg >> 6;
    int r   = rg & 63;

    size_t src = ((size_t)b * SEQ + rg) * DIM + c4 * 4;
    float4 kv = *(const float4*)(K + src);
    float4 vv = *(const float4*)(V + src);

    unsigned char* dst = g_kv + (size_t)(b * KTILES + kt) * KV_TILE_BYTES;
    uint32_t so = swz(r, c4);
    uint2 hi, lo;
    cvt_split(kv, hi, lo);
    *(uint2*)(dst + OFF_KHI + so) = hi;
    *(uint2*)(dst + OFF_KLO + so) = lo;
    uint2 vf;
    vf.x = pack_f16(vv.x, vv.y);
    vf.y = pack_f16(vv.z, vv.w);
    *(uint2*)(dst + OFF_V + so) = vf;
}

// ---------------- main kernel ----------------
__global__ __launch_bounds__(NTHREADS, 1)
void attn_mma_kernel(const float* __restrict__ Q, const float* __restrict__ scale,
                     float* __restrict__ Out)
{
    extern __shared__ char smem[];
    const uint32_t sb = smem_u32(smem);

    const int tid  = threadIdx.x;
    const int wid  = tid >> 5;
    const int lane = tid & 31;
    const int g    = lane >> 2;
    const int t4   = lane & 3;
    const int wr   = wid * 16;
    const int q0   = blockIdx.x * BM;
    const int b    = blockIdx.y;
    const int m7   = lane & 7;
    const float L2E = 1.4426950408889634f;

    const float* Qb = Q + (size_t)b * SEQ * DIM;
    const unsigned char* gkv = g_kv + (size_t)b * KTILES * KV_TILE_BYTES;

    // ---- prologue: prefetch tile 0 (48 KB) into stage 0 ----
    {
        #pragma unroll
        for (int u = 0; u < 12; u++) {
            int idx = tid + u * NTHREADS;
            cp_async16(sb + SM_STAGE0 + idx * 16, gkv + idx * 16);
        }
        asm volatile("cp.async.commit_group;" ::: "memory");
    }

    // ---- stage Q tile once: f32 -> bf16 hi/lo, swizzled ----
    for (int i = tid; i < BM * 32; i += NTHREADS) {
        int r = i >> 5, c4 = i & 31;
        float4 v = *(const float4*)(Qb + (size_t)(q0 + r) * DIM + c4 * 4);
        uint2 hi, lo; cvt_split(v, hi, lo);
        uint32_t so = swz(r, c4);
        *(uint2*)(smem + SM_QHI + so) = hi;
        *(uint2*)(smem + SM_QLO + so) = lo;
    }

    const uint32_t hcA = (lane >> 4) & 1;
    const uint32_t hcB = (lane >> 3) & 1;
    const uint32_t hcV = (lane >> 4) & 1;
    const uint32_t qrow  = (uint32_t)(wr + m7 + ((lane >> 3) & 1) * 8);
    const uint32_t krowl = (uint32_t)(m7 + ((lane >> 4) & 1) * 8);
    const uint32_t vrowl = (uint32_t)(lane & 15);
    const uint32_t qbase = sb + SM_QHI + qrow * 256;

    const float* sp0 = scale + (size_t)(q0 + wr + g) * SEQ + 2 * t4;
    const float* sp1 = sp0 + 8 * SEQ;

    float o[16][4];
    #pragma unroll
    for (int j = 0; j < 16; j++)
        { o[j][0] = 0.f; o[j][1] = 0.f; o[j][2] = 0.f; o[j][3] = 0.f; }
    float m0 = -1e30f, m1 = -1e30f, l0 = 0.f, l1 = 0.f;

    for (int kt = 0; kt < KTILES; kt++) {
        __syncthreads();

        if (kt + 1 < KTILES) {
            const unsigned char* srcb = gkv + (size_t)(kt + 1) * KV_TILE_BYTES;
            uint32_t dstb = sb + (((kt + 1) & 1) ? SM_STAGE1 : SM_STAGE0);
            #pragma unroll
            for (int u = 0; u < 12; u++) {
                int idx = tid + u * NTHREADS;
                cp_async16(dstb + idx * 16, srcb + idx * 16);
            }
            asm volatile("cp.async.commit_group;" ::: "memory");
            asm volatile("cp.async.wait_group 1;" ::: "memory");
        } else {
            asm volatile("cp.async.wait_group 0;" ::: "memory");
        }
        __syncthreads();

        const uint32_t stg = sb + ((kt & 1) ? SM_STAGE1 : SM_STAGE0);
        const uint32_t kbase = stg + OFF_KHI + krowl * 256;
        const uint32_t vbase = stg + OFF_V   + vrowl * 256;

        // scale rows -> regs (L2 hits, hidden under QK), log2e folded
        float2 scA[8], scB[8];
        #pragma unroll
        for (int j = 0; j < 8; j++) {
            float2 a = __ldg((const float2*)(sp0 + (size_t)kt * BN + 8 * j));
            float2 c = __ldg((const float2*)(sp1 + (size_t)kt * BN + 8 * j));
            scA[j] = make_float2(a.x * L2E, a.y * L2E);
            scB[j] = make_float2(c.x * L2E, c.y * L2E);
        }

        // ---- S = Q K^T : bf16 3-product split ----
        float s[8][4];
        #pragma unroll
        for (int j = 0; j < 8; j++)
            { s[j][0] = 0.f; s[j][1] = 0.f; s[j][2] = 0.f; s[j][3] = 0.f; }

        #pragma unroll
        for (int kc = 0; kc < 8; kc++) {
            uint32_t aoff = ((2u * kc + hcA) ^ m7) << 4;
            uint32_t boff = ((2u * kc + hcB) ^ m7) << 4;
            uint32_t ah[4], al[4], bh[4][4], bl[4][4];
            ldsm_x4(ah, qbase + aoff);
            ldsm_x4(al, qbase + 32768 + aoff);
            #pragma unroll
            for (int jp = 0; jp < 4; jp++) {
                uint32_t ka = kbase + jp * 4096u + boff;
                ldsm_x4(bh[jp], ka);
                ldsm_x4(bl[jp], ka + 16384);
            }
            #pragma unroll
            for (int jp = 0; jp < 4; jp++) {
                mma_bf16(s[2*jp],   ah, bh[jp][0], bh[jp][1]);
                mma_bf16(s[2*jp+1], ah, bh[jp][2], bh[jp][3]);
                mma_bf16(s[2*jp],   ah, bl[jp][0], bl[jp][1]);
                mma_bf16(s[2*jp+1], ah, bl[jp][2], bl[jp][3]);
                mma_bf16(s[2*jp],   al, bh[jp][0], bh[jp][1]);
                mma_bf16(s[2*jp+1], al, bh[jp][2], bh[jp][3]);
            }
        }

        // ---- scale (log2 domain) + online softmax via MUFU ex2 ----
        float mx0 = -1e30f, mx1 = -1e30f;
        #pragma unroll
        for (int j = 0; j < 8; j++) {
            s[j][0] *= scA[j].x; s[j][1] *= scA[j].y;
            s[j][2] *= scB[j].x; s[j][3] *= scB[j].y;
            mx0 = fmaxf(mx0, fmaxf(s[j][0], s[j][1]));
            mx1 = fmaxf(mx1, fmaxf(s[j][2], s[j][3]));
        }
        mx0 = fmaxf(mx0, __shfl_xor_sync(0xffffffffu, mx0, 1));
        mx0 = fmaxf(mx0, __shfl_xor_sync(0xffffffffu, mx0, 2));
        mx1 = fmaxf(mx1, __shfl_xor_sync(0xffffffffu, mx1, 1));
        mx1 = fmaxf(mx1, __shfl_xor_sync(0xffffffffu, mx1, 2));

        float mn0 = fmaxf(m0, mx0), mn1 = fmaxf(m1, mx1);
        float a0 = ex2f(m0 - mn0),  a1 = ex2f(m1 - mn1);
        float sum0 = 0.f, sum1 = 0.f;
        #pragma unroll
        for (int j = 0; j < 8; j++) {
            s[j][0] = ex2f(s[j][0] - mn0); sum0 += s[j][0];
            s[j][1] = ex2f(s[j][1] - mn0); sum0 += s[j][1];
            s[j][2] = ex2f(s[j][2] - mn1); sum1 += s[j][2];
            s[j][3] = ex2f(s[j][3] - mn1); sum1 += s[j][3];
        }
        l0 = l0 * a0 + sum0; m0 = mn0;
        l1 = l1 * a1 + sum1; m1 = mn1;
        if (a0 != 1.0f || a1 != 1.0f) {
            #pragma unroll
            for (int j = 0; j < 16; j++) {
                o[j][0] *= a0; o[j][1] *= a0;
                o[j][2] *= a1; o[j][3] *= a1;
            }
        }

        // ---- O += P V : fp16 single product ----
        #pragma unroll
        for (int c = 0; c < 4; c++) {
            uint32_t ph[4];
            ph[0] = pack_f16(s[2*c][0],   s[2*c][1]);
            ph[1] = pack_f16(s[2*c][2],   s[2*c][3]);
            ph[2] = pack_f16(s[2*c+1][0], s[2*c+1][1]);
            ph[3] = pack_f16(s[2*c+1][2], s[2*c+1][3]);
            #pragma unroll
            for (int half = 0; half < 2; half++) {
                uint32_t vh[4][4];
                #pragma unroll
                for (int q = 0; q < 4; q++) {
                    int jp = 4 * half + q;
                    uint32_t va = vbase + c * 4096u + (((2u * jp + hcV) ^ m7) << 4);
                    ldsm_x4_t(vh[q], va);
                }
                #pragma unroll
                for (int q = 0; q < 4; q++) {
                    int jp = 4 * half + q;
                    mma_f16(o[2*jp],   ph, vh[q][0], vh[q][1]);
                    mma_f16(o[2*jp+1], ph, vh[q][2], vh[q][3]);
                }
            }
        }
    }

    // ---- epilogue: reduce per-lane denominators across the t4 quad ----
    l0 += __shfl_xor_sync(0xffffffffu, l0, 1);
    l0 += __shfl_xor_sync(0xffffffffu, l0, 2);
    l1 += __shfl_xor_sync(0xffffffffu, l1, 1);
    l1 += __shfl_xor_sync(0xffffffffu, l1, 2);
    float inv0 = 1.f / l0, inv1 = 1.f / l1;
    float* out0 = Out + (size_t)((size_t)b * SEQ + q0 + wr + g) * DIM;
    float* out1 = out0 + 8 * DIM;
    #pragma unroll
    for (int j = 0; j < 16; j++) {
        int col = 8 * j + 2 * t4;
        *(float2*)(out0 + col) = make_float2(o[j][0] * inv0, o[j][1] * inv0);
        *(float2*)(out1 + col) = make_float2(o[j][2] * inv1, o[j][3] * inv1);
    }
}

extern "C" void kernel_launch(void* const* d_in, const int* in_sizes, int n_in,
                              void* d_out, int out_size)
{
    const float* Q     = (const float*)d_in[0];
    const float* K     = (const float*)d_in[1];
    const float* V     = (const float*)d_in[2];
    const float* scale = (const float*)d_in[3];
    float* O = (float*)d_out;

    kv_prepass<<<(BATCH * SEQ * 32) / 256, 256>>>(K, V);

    cudaFuncSetAttribute(attn_mma_kernel,
                         cudaFuncAttributeMaxDynamicSharedMemorySize, SM_TOTAL);
    dim3 grid(SEQ / BM, BATCH);
    attn_mma_kernel<<<grid, NTHREADS, SM_TOTAL>>>(Q, scale, O);
}